// round 11
// baseline (speedup 1.0000x reference)
#include <cuda_runtime.h>
#include <cuda_bf16.h>

// Problem constants
#define NN   32768
#define FIN  128
#define CC   256
#define HH   4
#define FH   64
#define EE   524288
#define BB   64
#define NPG  512
#define EPG  (EE / BB)
#define K1   256
#define K2   128

// ---------------- scratch (device globals; no allocation allowed) ----------
__device__ float    g_hlin[NN * CC];
__device__ float    g_hout[NN * CC];
__device__ float    g_es[NN * HH];
__device__ float    g_ed[NN * HH];
__device__ int      g_off[NN + 1];
__device__ int      g_csrc[EE];
__device__ float    g_sel[(BB * K1) * CC];
__device__ float    g_pool1[(BB * K1) * CC];
__device__ float    g_pool2[(BB * K2) * CC];

__device__ __forceinline__ float leaky(float x) { return x > 0.f ? x : 0.2f * x; }

// ---------------- packed f32x2 helpers (sm_103a FFMA2) ----------------------
__device__ __forceinline__ void ffma2(unsigned long long& d, unsigned long long a,
                                      unsigned long long b) {
    asm("fma.rn.f32x2 %0, %1, %2, %0;" : "+l"(d) : "l"(a), "l"(b));
}
__device__ __forceinline__ unsigned long long pack2(float x, float y) {
    unsigned long long r;
    asm("mov.b64 %0, {%1, %2};" : "=l"(r) : "f"(x), "f"(y));
    return r;
}
__device__ __forceinline__ float2 unpack2(unsigned long long v) {
    float2 r;
    asm("mov.b64 {%0, %1}, %2;" : "=f"(r.x), "=f"(r.y) : "l"(v));
    return r;
}

// ---------------- SGEMM (R3-proven inner loop) + optional es/ed epilogue ---
#define ASTRIDE 132
__global__ void __launch_bounds__(256, 2)
sgemm128(const float* __restrict__ A, const float* __restrict__ Bm,
         const float* __restrict__ bias, float* __restrict__ Cm,
         int M, int N, int K,
         const float* __restrict__ a_src, const float* __restrict__ a_dst,
         float* __restrict__ es, float* __restrict__ ed) {
    __shared__ float As[2][16][ASTRIDE];
    __shared__ float Bs[2][16][ASTRIDE];
    const int tid = threadIdx.x;
    const int row0 = blockIdx.y * 128;
    const int col0 = blockIdx.x * 128;
    const int ar = tid >> 2, ac = (tid & 3) << 2;
    const int br = tid >> 5, bc = (tid & 31) << 2;
    const int tx = tid & 15, ty = tid >> 4;
    const float* Ap = A + (size_t)(row0 + ar) * K;
    const float* Ap2 = Ap + (size_t)64 * K;

    float4 a0, a1, b0, b1;
    a0 = *(const float4*)(Ap + ac);
    a1 = *(const float4*)(Ap2 + ac);
    b0 = *(const float4*)(Bm + (size_t)br * N + col0 + bc);
    b1 = *(const float4*)(Bm + (size_t)(br + 8) * N + col0 + bc);
    As[0][ac + 0][ar] = a0.x; As[0][ac + 1][ar] = a0.y;
    As[0][ac + 2][ar] = a0.z; As[0][ac + 3][ar] = a0.w;
    As[0][ac + 0][ar + 64] = a1.x; As[0][ac + 1][ar + 64] = a1.y;
    As[0][ac + 2][ar + 64] = a1.z; As[0][ac + 3][ar + 64] = a1.w;
    *(float4*)&Bs[0][br][bc] = b0;
    *(float4*)&Bs[0][br + 8][bc] = b1;
    __syncthreads();

    unsigned long long acc2[8][4];
#pragma unroll
    for (int i = 0; i < 8; i++)
#pragma unroll
        for (int j = 0; j < 4; j++) acc2[i][j] = 0ull;

    const int ntiles = K >> 4;
    int buf = 0;
    for (int kt = 0; kt < ntiles; kt++) {
        if (kt + 1 < ntiles) {
            const int k0 = (kt + 1) << 4;
            a0 = *(const float4*)(Ap + k0 + ac);
            a1 = *(const float4*)(Ap2 + k0 + ac);
            b0 = *(const float4*)(Bm + (size_t)(k0 + br) * N + col0 + bc);
            b1 = *(const float4*)(Bm + (size_t)(k0 + br + 8) * N + col0 + bc);
        }
#pragma unroll
        for (int kk = 0; kk < 16; kk++) {
            float a[8], b[8];
            *(float4*)(a)     = *(const float4*)&As[buf][kk][ty * 8];
            *(float4*)(a + 4) = *(const float4*)&As[buf][kk][ty * 8 + 4];
            *(float4*)(b)     = *(const float4*)&Bs[buf][kk][tx * 8];
            *(float4*)(b + 4) = *(const float4*)&Bs[buf][kk][tx * 8 + 4];
            unsigned long long bp[4];
            bp[0] = pack2(b[0], b[1]); bp[1] = pack2(b[2], b[3]);
            bp[2] = pack2(b[4], b[5]); bp[3] = pack2(b[6], b[7]);
#pragma unroll
            for (int i = 0; i < 8; i++) {
                const unsigned long long ad = pack2(a[i], a[i]);
                ffma2(acc2[i][0], ad, bp[0]);
                ffma2(acc2[i][1], ad, bp[1]);
                ffma2(acc2[i][2], ad, bp[2]);
                ffma2(acc2[i][3], ad, bp[3]);
            }
        }
        if (kt + 1 < ntiles) {
            __syncthreads();
            const int nb = buf ^ 1;
            As[nb][ac + 0][ar] = a0.x; As[nb][ac + 1][ar] = a0.y;
            As[nb][ac + 2][ar] = a0.z; As[nb][ac + 3][ar] = a0.w;
            As[nb][ac + 0][ar + 64] = a1.x; As[nb][ac + 1][ar + 64] = a1.y;
            As[nb][ac + 2][ar + 64] = a1.z; As[nb][ac + 3][ar + 64] = a1.w;
            *(float4*)&Bs[nb][br][bc] = b0;
            *(float4*)&Bs[nb][br + 8][bc] = b1;
            __syncthreads();
            buf = nb;
        }
    }
    float bv[8];
    if (bias) {
        *(float4*)(bv)     = *(const float4*)&bias[col0 + tx * 8];
        *(float4*)(bv + 4) = *(const float4*)&bias[col0 + tx * 8 + 4];
    } else {
#pragma unroll
        for (int j = 0; j < 8; j++) bv[j] = 0.f;
    }
#pragma unroll
    for (int i = 0; i < 8; i++) {
        const int r = row0 + ty * 8 + i;
        const float2 c0 = unpack2(acc2[i][0]);
        const float2 c1 = unpack2(acc2[i][1]);
        const float2 c2 = unpack2(acc2[i][2]);
        const float2 c3 = unpack2(acc2[i][3]);
        float4 o0, o1;
        o0.x = c0.x + bv[0]; o0.y = c0.y + bv[1];
        o0.z = c1.x + bv[2]; o0.w = c1.y + bv[3];
        o1.x = c2.x + bv[4]; o1.y = c2.y + bv[5];
        o1.z = c3.x + bv[6]; o1.w = c3.y + bv[7];
        *(float4*)&Cm[(size_t)r * N + col0 + tx * 8] = o0;
        *(float4*)&Cm[(size_t)r * N + col0 + tx * 8 + 4] = o1;
    }

    // ---- optional fused es/ed epilogue (GAT GEMMs only) ----
    if (a_src) {
        const int head = (col0 >> 6) + (tx >> 3);
        const int coff = (tx & 7) * 8;
        float asv[8], adv[8];
        *(float4*)(asv)     = *(const float4*)&a_src[head * 64 + coff];
        *(float4*)(asv + 4) = *(const float4*)&a_src[head * 64 + coff + 4];
        *(float4*)(adv)     = *(const float4*)&a_dst[head * 64 + coff];
        *(float4*)(adv + 4) = *(const float4*)&a_dst[head * 64 + coff + 4];
#pragma unroll
        for (int i = 0; i < 8; i++) {
            const float2 c0 = unpack2(acc2[i][0]);
            const float2 c1 = unpack2(acc2[i][1]);
            const float2 c2 = unpack2(acc2[i][2]);
            const float2 c3 = unpack2(acc2[i][3]);
            const float v[8] = {c0.x, c0.y, c1.x, c1.y, c2.x, c2.y, c3.x, c3.y};
            float se = 0.f, de = 0.f;
#pragma unroll
            for (int j = 0; j < 8; j++) { se += v[j] * asv[j]; de += v[j] * adv[j]; }
#pragma unroll
            for (int m = 1; m < 8; m <<= 1) {
                se += __shfl_xor_sync(0xffffffffu, se, m);
                de += __shfl_xor_sync(0xffffffffu, de, m);
            }
            if ((tx & 7) == 0) {
                const int r = row0 + ty * 8 + i;
                es[r * HH + head] = se;
                ed[r * HH + head] = de;
            }
        }
    }
}

// ---------------- single-kernel CSR build (1 CTA per graph) -----------------
__global__ void __launch_bounds__(256)
csr_build(const int* __restrict__ ei) {
    __shared__ int cnt[NPG];
    __shared__ int sh[256];
    const int g = blockIdx.x, tid = threadIdx.x;
    const int ebase = g * EPG, nbase = g * NPG;
    cnt[tid] = 0; cnt[tid + 256] = 0;
    __syncthreads();
#pragma unroll
    for (int i = tid; i < EPG; i += 256)
        atomicAdd(&cnt[ei[EE + ebase + i] - nbase], 1);
    __syncthreads();
    const int c0 = cnt[2 * tid], c1 = cnt[2 * tid + 1];
    const int tot = c0 + c1;
    sh[tid] = tot;
    __syncthreads();
    for (int s = 1; s < 256; s <<= 1) {
        const int v = (tid >= s) ? sh[tid - s] : 0;
        __syncthreads();
        sh[tid] += v;
        __syncthreads();
    }
    const int base = sh[tid] - tot;
    g_off[nbase + 2 * tid]     = ebase + base;
    g_off[nbase + 2 * tid + 1] = ebase + base + c0;
    cnt[2 * tid] = base;
    cnt[2 * tid + 1] = base + c0;
    if (g == BB - 1 && tid == 0) g_off[NN] = EE;
    __syncthreads();
#pragma unroll
    for (int i = tid; i < EPG; i += 256) {
        const int d = ei[EE + ebase + i] - nbase;
        const int p = atomicAdd(&cnt[d], 1);
        g_csrc[ebase + p] = ei[ebase + i];
    }
}

// ---------------- fused softmax + aggregate + bias + ELU --------------------
// One warp per dst node. Per 32-edge chunk: lane-parallel weights staged to
// smem (float4 per edge) + src ids; aggregation loop uses broadcast LDS.128
// for weights and a depth-2 LDG software pipeline for neighbor rows.
__global__ void __launch_bounds__(256)
gat_fused(const int* __restrict__ off, const int* __restrict__ csrc,
          const float* __restrict__ es, const float* __restrict__ ed,
          const float* __restrict__ hlin, const float* __restrict__ bias,
          float* __restrict__ out) {
    __shared__ float4 wsm[8][32];
    __shared__ int    ssm[8][32];
    const int n = (blockIdx.x * blockDim.x + threadIdx.x) >> 5;
    const int w = threadIdx.x >> 5;
    const int lane = threadIdx.x & 31;
    if (n >= NN) return;

    const float4 edv = ((const float4*)ed)[n];
    const float4 esv = ((const float4*)es)[n];
    const float xs0 = __expf(leaky(esv.x + edv.x));
    const float xs1 = __expf(leaky(esv.y + edv.y));
    const float xs2 = __expf(leaky(esv.z + edv.z));
    const float xs3 = __expf(leaky(esv.w + edv.w));

    const int hi = lane >> 4;
    const float4* hn = (const float4*)(hlin + (size_t)n * CC);
    float4 acc0 = hn[lane];
    float4 acc1 = hn[32 + lane];
    const float sa0 = hi ? xs1 : xs0;
    const float sa1 = hi ? xs3 : xs2;
    acc0.x *= sa0; acc0.y *= sa0; acc0.z *= sa0; acc0.w *= sa0;
    acc1.x *= sa1; acc1.y *= sa1; acc1.z *= sa1; acc1.w *= sa1;

    float ts0 = 0.f, ts1 = 0.f, ts2 = 0.f, ts3 = 0.f;
    const int o0 = off[n], o1 = off[n + 1];
    for (int base = o0; base < o1; base += 32) {
        const int cnt = min(32, o1 - base);
        int s = 0;
        float t0 = 0.f, t1 = 0.f, t2 = 0.f, t3 = 0.f;
        if (lane < cnt) {
            s = csrc[base + lane];
            const float4 ess = ((const float4*)es)[s];
            t0 = __expf(leaky(ess.x + edv.x));
            t1 = __expf(leaky(ess.y + edv.y));
            t2 = __expf(leaky(ess.z + edv.z));
            t3 = __expf(leaky(ess.w + edv.w));
        }
        ts0 += t0; ts1 += t1; ts2 += t2; ts3 += t3;
        wsm[w][lane] = make_float4(t0, t1, t2, t3);
        ssm[w][lane] = s;
        __syncwarp();

        // depth-2 pipelined aggregation
        const float4* h0p = (const float4*)(hlin + (size_t)ssm[w][0] * CC);
        float4 va0 = h0p[lane], va1 = h0p[32 + lane];
        float4 vb0 = va0, vb1 = va1;
        if (cnt > 1) {
            const float4* h1p = (const float4*)(hlin + (size_t)ssm[w][1] * CC);
            vb0 = h1p[lane]; vb1 = h1p[32 + lane];
        }
        float4 wv = wsm[w][0];
        for (int e = 0; e < cnt; e++) {
            const float4 u0 = va0, u1 = va1;
            const float4 wc = wv;
            va0 = vb0; va1 = vb1;
            if (e + 2 < cnt) {
                const float4* hp = (const float4*)(hlin + (size_t)ssm[w][e + 2] * CC);
                vb0 = hp[lane]; vb1 = hp[32 + lane];
            }
            if (e + 1 < cnt) wv = wsm[w][e + 1];
            const float aw0 = hi ? wc.y : wc.x;
            const float aw1 = hi ? wc.w : wc.z;
            acc0.x += aw0 * u0.x; acc0.y += aw0 * u0.y;
            acc0.z += aw0 * u0.z; acc0.w += aw0 * u0.w;
            acc1.x += aw1 * u1.x; acc1.y += aw1 * u1.y;
            acc1.z += aw1 * u1.z; acc1.w += aw1 * u1.w;
        }
        __syncwarp();
    }
#pragma unroll
    for (int o = 16; o; o >>= 1) {
        ts0 += __shfl_xor_sync(0xffffffffu, ts0, o);
        ts1 += __shfl_xor_sync(0xffffffffu, ts1, o);
        ts2 += __shfl_xor_sync(0xffffffffu, ts2, o);
        ts3 += __shfl_xor_sync(0xffffffffu, ts3, o);
    }
    const float di0 = 1.f / (xs0 + ts0 + 1e-16f);
    const float di1 = 1.f / (xs1 + ts1 + 1e-16f);
    const float di2 = 1.f / (xs2 + ts2 + 1e-16f);
    const float di3 = 1.f / (xs3 + ts3 + 1e-16f);
    const float d0 = hi ? di1 : di0;
    const float d1 = hi ? di3 : di2;

    const float4 bv0 = ((const float4*)bias)[lane];
    const float4 bv1 = ((const float4*)bias)[32 + lane];
    float4 o0v, o1v;
    o0v.x = acc0.x * d0 + bv0.x; o0v.y = acc0.y * d0 + bv0.y;
    o0v.z = acc0.z * d0 + bv0.z; o0v.w = acc0.w * d0 + bv0.w;
    o1v.x = acc1.x * d1 + bv1.x; o1v.y = acc1.y * d1 + bv1.y;
    o1v.z = acc1.z * d1 + bv1.z; o1v.w = acc1.w * d1 + bv1.w;
    o0v.x = o0v.x > 0.f ? o0v.x : (__expf(o0v.x) - 1.f);
    o0v.y = o0v.y > 0.f ? o0v.y : (__expf(o0v.y) - 1.f);
    o0v.z = o0v.z > 0.f ? o0v.z : (__expf(o0v.z) - 1.f);
    o0v.w = o0v.w > 0.f ? o0v.w : (__expf(o0v.w) - 1.f);
    o1v.x = o1v.x > 0.f ? o1v.x : (__expf(o1v.x) - 1.f);
    o1v.y = o1v.y > 0.f ? o1v.y : (__expf(o1v.y) - 1.f);
    o1v.z = o1v.z > 0.f ? o1v.z : (__expf(o1v.z) - 1.f);
    o1v.w = o1v.w > 0.f ? o1v.w : (__expf(o1v.w) - 1.f);
    ((float4*)out)[(size_t)n * 64 + lane]      = o0v;
    ((float4*)out)[(size_t)n * 64 + 32 + lane] = o1v;
}

// ---------------- fused pooling: score + top-k + gather ---------------------
template <int NPB, int KSEL>
__global__ void pool_fused(const float* __restrict__ X, const float* __restrict__ sw,
                           float* __restrict__ selb) {
    __shared__ float sv[NPB];
    __shared__ int si[NPB];
    const int b = blockIdx.x, t = threadIdx.x;
    const int wid = t >> 5, lane = t & 31;

#pragma unroll
    for (int rr = 0; rr < 32; rr++) {
        const int local = wid * 32 + rr;
        const float* xp = X + (size_t)(b * NPB + local) * CC;
        float s = 0.f;
#pragma unroll
        for (int c = 0; c < CC / 32; c++) s += xp[lane + c * 32] * sw[lane + c * 32];
#pragma unroll
        for (int o = 16; o; o >>= 1) s += __shfl_xor_sync(0xffffffffu, s, o);
        if (lane == 0) { sv[local] = s; si[local] = local; }
    }
    __syncthreads();

    for (int k = 2; k <= NPB; k <<= 1) {
        for (int j = k >> 1; j > 0; j >>= 1) {
            const int ixj = t ^ j;
            if (ixj > t) {
                const bool desc = ((t & k) == 0);
                const float a = sv[t], c = sv[ixj];
                if ((a < c) == desc) {
                    sv[t] = c; sv[ixj] = a;
                    const int tmp = si[t]; si[t] = si[ixj]; si[ixj] = tmp;
                }
            }
            __syncthreads();
        }
    }

    for (int idx = t; idx < KSEL * 64; idx += NPB) {
        const int r = idx >> 6, q = idx & 63;
        const int src = b * NPB + si[r];
        ((float4*)selb)[(size_t)(b * KSEL + r) * 64 + q] =
            ((const float4*)X)[(size_t)src * 64 + q];
    }
}

// ---------------- fused readout: mean + fc1(relu) + fc2 + log_softmax -------
__global__ void __launch_bounds__(256)
readout_fused(const float* __restrict__ X, const float* __restrict__ c1w,
              const float* __restrict__ c1b, const float* __restrict__ c2w,
              const float* __restrict__ c2b, float* __restrict__ out) {
    __shared__ float gm[CC];
    __shared__ float f1[64];
    const int b = blockIdx.x, t = threadIdx.x;
    const int wid = t >> 5, lane = t & 31;

    float s = 0.f;
    const float* xp = X + (size_t)b * K2 * CC + t;
#pragma unroll 4
    for (int r = 0; r < K2; r++) s += xp[r * CC];
    gm[t] = s * (1.f / K2);
    __syncthreads();

#pragma unroll
    for (int oo = 0; oo < 8; oo++) {
        const int o = wid * 8 + oo;
        float acc = 0.f;
#pragma unroll
        for (int c = 0; c < CC / 32; c++)
            acc += gm[lane + c * 32] * c1w[(lane + c * 32) * 64 + o];
#pragma unroll
        for (int off = 16; off; off >>= 1) acc += __shfl_xor_sync(0xffffffffu, acc, off);
        if (lane == 0) {
            const float v = acc + c1b[o];
            f1[o] = v > 0.f ? v : 0.f;
        }
    }
    __syncthreads();

    if (wid == 0) {
        float l0 = 0.f, l1 = 0.f;
#pragma unroll
        for (int k = lane; k < 64; k += 32) {
            const float v = f1[k];
            l0 += v * c2w[k * 2 + 0];
            l1 += v * c2w[k * 2 + 1];
        }
#pragma unroll
        for (int off = 16; off; off >>= 1) {
            l0 += __shfl_xor_sync(0xffffffffu, l0, off);
            l1 += __shfl_xor_sync(0xffffffffu, l1, off);
        }
        if (lane == 0) {
            l0 += c2b[0]; l1 += c2b[1];
            const float mm = fmaxf(l0, l1);
            const float lse = mm + logf(__expf(l0 - mm) + __expf(l1 - mm));
            out[b * 2 + 0] = l0 - lse;
            out[b * 2 + 1] = l1 - lse;
        }
    }
}

// ---------------- host orchestration ----------------------------------------
static float* sym(const void* s) {
    void* p = nullptr;
    cudaGetSymbolAddress(&p, (const void*)s);
    return (float*)p;
}

extern "C" void kernel_launch(void* const* d_in, const int* in_sizes, int n_in,
                              void* d_out, int out_size) {
    const float* x      = (const float*)d_in[0];
    const int*   ei     = (const int*)  d_in[1];
    const float* W1     = (const float*)d_in[3];
    const float* asrc1  = (const float*)d_in[4];
    const float* adst1  = (const float*)d_in[5];
    const float* b1     = (const float*)d_in[6];
    const float* W2     = (const float*)d_in[7];
    const float* asrc2  = (const float*)d_in[8];
    const float* adst2  = (const float*)d_in[9];
    const float* b2     = (const float*)d_in[10];
    const float* p1_sw  = (const float*)d_in[11];
    const float* p1_tw  = (const float*)d_in[13];
    const float* p1_tb  = (const float*)d_in[14];
    const float* p2_sw  = (const float*)d_in[15];
    const float* p2_tw  = (const float*)d_in[17];
    const float* p2_tb  = (const float*)d_in[18];
    const float* c1w    = (const float*)d_in[19];
    const float* c1b    = (const float*)d_in[20];
    const float* c2w    = (const float*)d_in[21];
    const float* c2b    = (const float*)d_in[22];
    float* out = (float*)d_out;

    float*    hlin  = sym(g_hlin);
    float*    hout  = sym(g_hout);
    float*    es    = sym(g_es);
    float*    ed    = sym(g_ed);
    int*      off   = (int*)sym(g_off);
    int*      csrc  = (int*)sym(g_csrc);
    float*    selb  = sym(g_sel);
    float*    pool1 = sym(g_pool1);
    float*    pool2 = sym(g_pool2);

    dim3 t256(256);

    // ---- CSR build ----
    csr_build<<<BB, t256>>>(ei);

    // ---- GAT layer 1 (GEMM emits es/ed in epilogue) ----
    sgemm128<<<dim3(CC / 128, NN / 128), t256>>>(x, W1, nullptr, hlin, NN, CC, FIN,
                                                 asrc1, adst1, es, ed);
    gat_fused<<<(NN * 32) / 256, t256>>>(off, csrc, es, ed, hlin, b1, hout);

    // ---- GAT layer 2 ----
    sgemm128<<<dim3(CC / 128, NN / 128), t256>>>(hout, W2, nullptr, hlin, NN, CC, CC,
                                                 asrc2, adst2, es, ed);
    gat_fused<<<(NN * 32) / 256, t256>>>(off, csrc, es, ed, hlin, b2, hout);

    // ---- Pool 1 (top-256 of 512 per graph) ----
    pool_fused<NPG, K1><<<BB, NPG>>>(hout, p1_sw, selb);
    sgemm128<<<dim3(CC / 128, (BB * K1) / 128), t256>>>(selb, p1_tw, p1_tb, pool1,
                                                        BB * K1, CC, CC,
                                                        nullptr, nullptr, nullptr, nullptr);

    // ---- Pool 2 (top-128 of 256 per graph) ----
    pool_fused<K1, K2><<<BB, K1>>>(pool1, p2_sw, selb);
    sgemm128<<<dim3(CC / 128, (BB * K2) / 128), t256>>>(selb, p2_tw, p2_tb, pool2,
                                                        BB * K2, CC, CC,
                                                        nullptr, nullptr, nullptr, nullptr);

    // ---- readout ----
    readout_fused<<<BB, t256>>>(pool2, c1w, c1b, c2w, c2b, out);
}

// round 12
// speedup vs baseline: 1.0200x; 1.0200x over previous
#include <cuda_runtime.h>
#include <cuda_bf16.h>

// Problem constants
#define NN   32768
#define FIN  128
#define CC   256
#define HH   4
#define FH   64
#define EE   524288
#define BB   64
#define NPG  512
#define EPG  (EE / BB)
#define K1   256
#define K2   128

// ---------------- scratch (device globals; no allocation allowed) ----------
__device__ float    g_hlin[NN * CC];
__device__ float    g_hout[NN * CC];
__device__ float    g_es[NN * HH];
__device__ float    g_ed[NN * HH];
__device__ int      g_off[NN + 1];
__device__ int      g_csrc[EE];
__device__ float    g_sel[(BB * K1) * CC];
__device__ float    g_pool1[(BB * K1) * CC];
__device__ float    g_pool2[(BB * K2) * CC];

__device__ __forceinline__ float leaky(float x) { return x > 0.f ? x : 0.2f * x; }

// ---------------- packed f32x2 helpers (sm_103a FFMA2) ----------------------
__device__ __forceinline__ void ffma2(unsigned long long& d, unsigned long long a,
                                      unsigned long long b) {
    asm("fma.rn.f32x2 %0, %1, %2, %0;" : "+l"(d) : "l"(a), "l"(b));
}
__device__ __forceinline__ unsigned long long pack2(float x, float y) {
    unsigned long long r;
    asm("mov.b64 %0, {%1, %2};" : "=l"(r) : "f"(x), "f"(y));
    return r;
}
__device__ __forceinline__ float2 unpack2(unsigned long long v) {
    float2 r;
    asm("mov.b64 {%0, %1}, %2;" : "=f"(r.x), "=f"(r.y) : "l"(v));
    return r;
}

// ---------------- SGEMM: 64x128 tile, 128 threads, 4 CTAs/SM ----------------
// C[M,N]=A@B (+bias); same 8x8 FFMA2 microtile and inner loop as the proven
// 128x128 version, but 4 independent sync domains per SM to cut barrier
// stalls. Optional fused es/ed epilogue for the GAT GEMMs (N==256).
// Requires M%64==0, N%128==0, K%16==0.
#define ASTR 68
#define BSTR 132
__global__ void __launch_bounds__(128, 4)
sgemm64(const float* __restrict__ A, const float* __restrict__ Bm,
        const float* __restrict__ bias, float* __restrict__ Cm,
        int M, int N, int K,
        const float* __restrict__ a_src, const float* __restrict__ a_dst,
        float* __restrict__ es, float* __restrict__ ed) {
    __shared__ float As[2][16][ASTR];
    __shared__ float Bs[2][16][BSTR];
    const int tid = threadIdx.x;
    const int row0 = blockIdx.y * 64;
    const int col0 = blockIdx.x * 128;
    const int ar = tid >> 1, ac = (tid & 1) << 3;    // A: row ar, cols ac..ac+7
    const int br = tid >> 5, bc = (tid & 31) << 2;   // B: rows br,br+4,br+8,br+12
    const int tx = tid & 15, ty = tid >> 4;          // 16 x 8 thread grid
    const float* Ap = A + (size_t)(row0 + ar) * K;

    float4 a0, a1, b0, b1, b2, b3;
    a0 = *(const float4*)(Ap + ac);
    a1 = *(const float4*)(Ap + ac + 4);
    b0 = *(const float4*)(Bm + (size_t)(br)      * N + col0 + bc);
    b1 = *(const float4*)(Bm + (size_t)(br + 4)  * N + col0 + bc);
    b2 = *(const float4*)(Bm + (size_t)(br + 8)  * N + col0 + bc);
    b3 = *(const float4*)(Bm + (size_t)(br + 12) * N + col0 + bc);
    As[0][ac + 0][ar] = a0.x; As[0][ac + 1][ar] = a0.y;
    As[0][ac + 2][ar] = a0.z; As[0][ac + 3][ar] = a0.w;
    As[0][ac + 4][ar] = a1.x; As[0][ac + 5][ar] = a1.y;
    As[0][ac + 6][ar] = a1.z; As[0][ac + 7][ar] = a1.w;
    *(float4*)&Bs[0][br][bc]      = b0;
    *(float4*)&Bs[0][br + 4][bc]  = b1;
    *(float4*)&Bs[0][br + 8][bc]  = b2;
    *(float4*)&Bs[0][br + 12][bc] = b3;
    __syncthreads();

    unsigned long long acc2[8][4];
#pragma unroll
    for (int i = 0; i < 8; i++)
#pragma unroll
        for (int j = 0; j < 4; j++) acc2[i][j] = 0ull;

    const int ntiles = K >> 4;
    int buf = 0;
    for (int kt = 0; kt < ntiles; kt++) {
        if (kt + 1 < ntiles) {
            const int k0 = (kt + 1) << 4;
            a0 = *(const float4*)(Ap + k0 + ac);
            a1 = *(const float4*)(Ap + k0 + ac + 4);
            b0 = *(const float4*)(Bm + (size_t)(k0 + br)      * N + col0 + bc);
            b1 = *(const float4*)(Bm + (size_t)(k0 + br + 4)  * N + col0 + bc);
            b2 = *(const float4*)(Bm + (size_t)(k0 + br + 8)  * N + col0 + bc);
            b3 = *(const float4*)(Bm + (size_t)(k0 + br + 12) * N + col0 + bc);
        }
#pragma unroll
        for (int kk = 0; kk < 16; kk++) {
            float a[8], b[8];
            *(float4*)(a)     = *(const float4*)&As[buf][kk][ty * 8];
            *(float4*)(a + 4) = *(const float4*)&As[buf][kk][ty * 8 + 4];
            *(float4*)(b)     = *(const float4*)&Bs[buf][kk][tx * 8];
            *(float4*)(b + 4) = *(const float4*)&Bs[buf][kk][tx * 8 + 4];
            unsigned long long bp[4];
            bp[0] = pack2(b[0], b[1]); bp[1] = pack2(b[2], b[3]);
            bp[2] = pack2(b[4], b[5]); bp[3] = pack2(b[6], b[7]);
#pragma unroll
            for (int i = 0; i < 8; i++) {
                const unsigned long long ad = pack2(a[i], a[i]);
                ffma2(acc2[i][0], ad, bp[0]);
                ffma2(acc2[i][1], ad, bp[1]);
                ffma2(acc2[i][2], ad, bp[2]);
                ffma2(acc2[i][3], ad, bp[3]);
            }
        }
        if (kt + 1 < ntiles) {
            __syncthreads();
            const int nb = buf ^ 1;
            As[nb][ac + 0][ar] = a0.x; As[nb][ac + 1][ar] = a0.y;
            As[nb][ac + 2][ar] = a0.z; As[nb][ac + 3][ar] = a0.w;
            As[nb][ac + 4][ar] = a1.x; As[nb][ac + 5][ar] = a1.y;
            As[nb][ac + 6][ar] = a1.z; As[nb][ac + 7][ar] = a1.w;
            *(float4*)&Bs[nb][br][bc]      = b0;
            *(float4*)&Bs[nb][br + 4][bc]  = b1;
            *(float4*)&Bs[nb][br + 8][bc]  = b2;
            *(float4*)&Bs[nb][br + 12][bc] = b3;
            __syncthreads();
            buf = nb;
        }
    }
    float bv[8];
    if (bias) {
        *(float4*)(bv)     = *(const float4*)&bias[col0 + tx * 8];
        *(float4*)(bv + 4) = *(const float4*)&bias[col0 + tx * 8 + 4];
    } else {
#pragma unroll
        for (int j = 0; j < 8; j++) bv[j] = 0.f;
    }
#pragma unroll
    for (int i = 0; i < 8; i++) {
        const int r = row0 + ty * 8 + i;
        const float2 c0 = unpack2(acc2[i][0]);
        const float2 c1 = unpack2(acc2[i][1]);
        const float2 c2 = unpack2(acc2[i][2]);
        const float2 c3 = unpack2(acc2[i][3]);
        float4 o0, o1;
        o0.x = c0.x + bv[0]; o0.y = c0.y + bv[1];
        o0.z = c1.x + bv[2]; o0.w = c1.y + bv[3];
        o1.x = c2.x + bv[4]; o1.y = c2.y + bv[5];
        o1.z = c3.x + bv[6]; o1.w = c3.y + bv[7];
        *(float4*)&Cm[(size_t)r * N + col0 + tx * 8] = o0;
        *(float4*)&Cm[(size_t)r * N + col0 + tx * 8 + 4] = o1;
    }

    // ---- optional fused es/ed epilogue (GAT GEMMs only) ----
    if (a_src) {
        const int head = (col0 >> 6) + (tx >> 3);
        const int coff = (tx & 7) * 8;
        float asv[8], adv[8];
        *(float4*)(asv)     = *(const float4*)&a_src[head * 64 + coff];
        *(float4*)(asv + 4) = *(const float4*)&a_src[head * 64 + coff + 4];
        *(float4*)(adv)     = *(const float4*)&a_dst[head * 64 + coff];
        *(float4*)(adv + 4) = *(const float4*)&a_dst[head * 64 + coff + 4];
#pragma unroll
        for (int i = 0; i < 8; i++) {
            const float2 c0 = unpack2(acc2[i][0]);
            const float2 c1 = unpack2(acc2[i][1]);
            const float2 c2 = unpack2(acc2[i][2]);
            const float2 c3 = unpack2(acc2[i][3]);
            const float v[8] = {c0.x, c0.y, c1.x, c1.y, c2.x, c2.y, c3.x, c3.y};
            float se = 0.f, de = 0.f;
#pragma unroll
            for (int j = 0; j < 8; j++) { se += v[j] * asv[j]; de += v[j] * adv[j]; }
#pragma unroll
            for (int m = 1; m < 8; m <<= 1) {
                se += __shfl_xor_sync(0xffffffffu, se, m);
                de += __shfl_xor_sync(0xffffffffu, de, m);
            }
            if ((tx & 7) == 0) {
                const int r = row0 + ty * 8 + i;
                es[r * HH + head] = se;
                ed[r * HH + head] = de;
            }
        }
    }
}

// ---------------- single-kernel CSR build (1 CTA per graph) -----------------
__global__ void __launch_bounds__(256)
csr_build(const int* __restrict__ ei) {
    __shared__ int cnt[NPG];
    __shared__ int sh[256];
    const int g = blockIdx.x, tid = threadIdx.x;
    const int ebase = g * EPG, nbase = g * NPG;
    cnt[tid] = 0; cnt[tid + 256] = 0;
    __syncthreads();
#pragma unroll
    for (int i = tid; i < EPG; i += 256)
        atomicAdd(&cnt[ei[EE + ebase + i] - nbase], 1);
    __syncthreads();
    const int c0 = cnt[2 * tid], c1 = cnt[2 * tid + 1];
    const int tot = c0 + c1;
    sh[tid] = tot;
    __syncthreads();
    for (int s = 1; s < 256; s <<= 1) {
        const int v = (tid >= s) ? sh[tid - s] : 0;
        __syncthreads();
        sh[tid] += v;
        __syncthreads();
    }
    const int base = sh[tid] - tot;
    g_off[nbase + 2 * tid]     = ebase + base;
    g_off[nbase + 2 * tid + 1] = ebase + base + c0;
    cnt[2 * tid] = base;
    cnt[2 * tid + 1] = base + c0;
    if (g == BB - 1 && tid == 0) g_off[NN] = EE;
    __syncthreads();
#pragma unroll
    for (int i = tid; i < EPG; i += 256) {
        const int d = ei[EE + ebase + i] - nbase;
        const int p = atomicAdd(&cnt[d], 1);
        g_csrc[ebase + p] = ei[ebase + i];
    }
}

// ---------------- fused softmax + aggregate + bias + ELU (R10-proven) -------
__global__ void __launch_bounds__(256)
gat_fused(const int* __restrict__ off, const int* __restrict__ csrc,
          const float* __restrict__ es, const float* __restrict__ ed,
          const float* __restrict__ hlin, const float* __restrict__ bias,
          float* __restrict__ out) {
    const int n = (blockIdx.x * blockDim.x + threadIdx.x) >> 5;
    const int lane = threadIdx.x & 31;
    if (n >= NN) return;

    const float4 edv = ((const float4*)ed)[n];
    const float4 esv = ((const float4*)es)[n];
    const float xs0 = __expf(leaky(esv.x + edv.x));
    const float xs1 = __expf(leaky(esv.y + edv.y));
    const float xs2 = __expf(leaky(esv.z + edv.z));
    const float xs3 = __expf(leaky(esv.w + edv.w));

    const int hi = lane >> 4;
    const float4* hn = (const float4*)(hlin + (size_t)n * CC);
    float4 acc0 = hn[lane];
    float4 acc1 = hn[32 + lane];
    const float sa0 = hi ? xs1 : xs0;
    const float sa1 = hi ? xs3 : xs2;
    acc0.x *= sa0; acc0.y *= sa0; acc0.z *= sa0; acc0.w *= sa0;
    acc1.x *= sa1; acc1.y *= sa1; acc1.z *= sa1; acc1.w *= sa1;

    float ts0 = 0.f, ts1 = 0.f, ts2 = 0.f, ts3 = 0.f;
    const int o0 = off[n], o1 = off[n + 1];
    for (int base = o0; base < o1; base += 32) {
        const int cnt = min(32, o1 - base);
        int s = 0;
        float t0 = 0.f, t1 = 0.f, t2 = 0.f, t3 = 0.f;
        if (lane < cnt) {
            s = csrc[base + lane];
            const float4 ess = ((const float4*)es)[s];
            t0 = __expf(leaky(ess.x + edv.x));
            t1 = __expf(leaky(ess.y + edv.y));
            t2 = __expf(leaky(ess.z + edv.z));
            t3 = __expf(leaky(ess.w + edv.w));
        }
        ts0 += t0; ts1 += t1; ts2 += t2; ts3 += t3;

        int se = __shfl_sync(0xffffffffu, s, 0);
        const float4* hs = (const float4*)(hlin + (size_t)se * CC);
        float4 v0n = hs[lane], v1n = hs[32 + lane];
        for (int e = 0; e < cnt; e++) {
            const float4 v0 = v0n, v1 = v1n;
            const float w0 = __shfl_sync(0xffffffffu, t0, e);
            const float w1 = __shfl_sync(0xffffffffu, t1, e);
            const float w2 = __shfl_sync(0xffffffffu, t2, e);
            const float w3 = __shfl_sync(0xffffffffu, t3, e);
            if (e + 1 < cnt) {
                se = __shfl_sync(0xffffffffu, s, e + 1);
                const float4* hsn = (const float4*)(hlin + (size_t)se * CC);
                v0n = hsn[lane]; v1n = hsn[32 + lane];
            }
            const float aw0 = hi ? w1 : w0;
            const float aw1 = hi ? w3 : w2;
            acc0.x += aw0 * v0.x; acc0.y += aw0 * v0.y;
            acc0.z += aw0 * v0.z; acc0.w += aw0 * v0.w;
            acc1.x += aw1 * v1.x; acc1.y += aw1 * v1.y;
            acc1.z += aw1 * v1.z; acc1.w += aw1 * v1.w;
        }
    }
#pragma unroll
    for (int o = 16; o; o >>= 1) {
        ts0 += __shfl_xor_sync(0xffffffffu, ts0, o);
        ts1 += __shfl_xor_sync(0xffffffffu, ts1, o);
        ts2 += __shfl_xor_sync(0xffffffffu, ts2, o);
        ts3 += __shfl_xor_sync(0xffffffffu, ts3, o);
    }
    const float di0 = 1.f / (xs0 + ts0 + 1e-16f);
    const float di1 = 1.f / (xs1 + ts1 + 1e-16f);
    const float di2 = 1.f / (xs2 + ts2 + 1e-16f);
    const float di3 = 1.f / (xs3 + ts3 + 1e-16f);
    const float d0 = hi ? di1 : di0;
    const float d1 = hi ? di3 : di2;

    const float4 bv0 = ((const float4*)bias)[lane];
    const float4 bv1 = ((const float4*)bias)[32 + lane];
    float4 o0v, o1v;
    o0v.x = acc0.x * d0 + bv0.x; o0v.y = acc0.y * d0 + bv0.y;
    o0v.z = acc0.z * d0 + bv0.z; o0v.w = acc0.w * d0 + bv0.w;
    o1v.x = acc1.x * d1 + bv1.x; o1v.y = acc1.y * d1 + bv1.y;
    o1v.z = acc1.z * d1 + bv1.z; o1v.w = acc1.w * d1 + bv1.w;
    o0v.x = o0v.x > 0.f ? o0v.x : (__expf(o0v.x) - 1.f);
    o0v.y = o0v.y > 0.f ? o0v.y : (__expf(o0v.y) - 1.f);
    o0v.z = o0v.z > 0.f ? o0v.z : (__expf(o0v.z) - 1.f);
    o0v.w = o0v.w > 0.f ? o0v.w : (__expf(o0v.w) - 1.f);
    o1v.x = o1v.x > 0.f ? o1v.x : (__expf(o1v.x) - 1.f);
    o1v.y = o1v.y > 0.f ? o1v.y : (__expf(o1v.y) - 1.f);
    o1v.z = o1v.z > 0.f ? o1v.z : (__expf(o1v.z) - 1.f);
    o1v.w = o1v.w > 0.f ? o1v.w : (__expf(o1v.w) - 1.f);
    ((float4*)out)[(size_t)n * 64 + lane]      = o0v;
    ((float4*)out)[(size_t)n * 64 + 32 + lane] = o1v;
}

// ---------------- fused pooling: score + top-k + gather ---------------------
template <int NPB, int KSEL>
__global__ void pool_fused(const float* __restrict__ X, const float* __restrict__ sw,
                           float* __restrict__ selb) {
    __shared__ float sv[NPB];
    __shared__ int si[NPB];
    const int b = blockIdx.x, t = threadIdx.x;
    const int wid = t >> 5, lane = t & 31;

#pragma unroll
    for (int rr = 0; rr < 32; rr++) {
        const int local = wid * 32 + rr;
        const float* xp = X + (size_t)(b * NPB + local) * CC;
        float s = 0.f;
#pragma unroll
        for (int c = 0; c < CC / 32; c++) s += xp[lane + c * 32] * sw[lane + c * 32];
#pragma unroll
        for (int o = 16; o; o >>= 1) s += __shfl_xor_sync(0xffffffffu, s, o);
        if (lane == 0) { sv[local] = s; si[local] = local; }
    }
    __syncthreads();

    for (int k = 2; k <= NPB; k <<= 1) {
        for (int j = k >> 1; j > 0; j >>= 1) {
            const int ixj = t ^ j;
            if (ixj > t) {
                const bool desc = ((t & k) == 0);
                const float a = sv[t], c = sv[ixj];
                if ((a < c) == desc) {
                    sv[t] = c; sv[ixj] = a;
                    const int tmp = si[t]; si[t] = si[ixj]; si[ixj] = tmp;
                }
            }
            __syncthreads();
        }
    }

    for (int idx = t; idx < KSEL * 64; idx += NPB) {
        const int r = idx >> 6, q = idx & 63;
        const int src = b * NPB + si[r];
        ((float4*)selb)[(size_t)(b * KSEL + r) * 64 + q] =
            ((const float4*)X)[(size_t)src * 64 + q];
    }
}

// ---------------- fused readout: mean + fc1(relu) + fc2 + log_softmax -------
__global__ void __launch_bounds__(256)
readout_fused(const float* __restrict__ X, const float* __restrict__ c1w,
              const float* __restrict__ c1b, const float* __restrict__ c2w,
              const float* __restrict__ c2b, float* __restrict__ out) {
    __shared__ float gm[CC];
    __shared__ float f1[64];
    const int b = blockIdx.x, t = threadIdx.x;
    const int wid = t >> 5, lane = t & 31;

    float s = 0.f;
    const float* xp = X + (size_t)b * K2 * CC + t;
#pragma unroll 4
    for (int r = 0; r < K2; r++) s += xp[r * CC];
    gm[t] = s * (1.f / K2);
    __syncthreads();

#pragma unroll
    for (int oo = 0; oo < 8; oo++) {
        const int o = wid * 8 + oo;
        float acc = 0.f;
#pragma unroll
        for (int c = 0; c < CC / 32; c++)
            acc += gm[lane + c * 32] * c1w[(lane + c * 32) * 64 + o];
#pragma unroll
        for (int off = 16; off; off >>= 1) acc += __shfl_xor_sync(0xffffffffu, acc, off);
        if (lane == 0) {
            const float v = acc + c1b[o];
            f1[o] = v > 0.f ? v : 0.f;
        }
    }
    __syncthreads();

    if (wid == 0) {
        float l0 = 0.f, l1 = 0.f;
#pragma unroll
        for (int k = lane; k < 64; k += 32) {
            const float v = f1[k];
            l0 += v * c2w[k * 2 + 0];
            l1 += v * c2w[k * 2 + 1];
        }
#pragma unroll
        for (int off = 16; off; off >>= 1) {
            l0 += __shfl_xor_sync(0xffffffffu, l0, off);
            l1 += __shfl_xor_sync(0xffffffffu, l1, off);
        }
        if (lane == 0) {
            l0 += c2b[0]; l1 += c2b[1];
            const float mm = fmaxf(l0, l1);
            const float lse = mm + logf(__expf(l0 - mm) + __expf(l1 - mm));
            out[b * 2 + 0] = l0 - lse;
            out[b * 2 + 1] = l1 - lse;
        }
    }
}

// ---------------- host orchestration ----------------------------------------
static float* sym(const void* s) {
    void* p = nullptr;
    cudaGetSymbolAddress(&p, (const void*)s);
    return (float*)p;
}

extern "C" void kernel_launch(void* const* d_in, const int* in_sizes, int n_in,
                              void* d_out, int out_size) {
    const float* x      = (const float*)d_in[0];
    const int*   ei     = (const int*)  d_in[1];
    const float* W1     = (const float*)d_in[3];
    const float* asrc1  = (const float*)d_in[4];
    const float* adst1  = (const float*)d_in[5];
    const float* b1     = (const float*)d_in[6];
    const float* W2     = (const float*)d_in[7];
    const float* asrc2  = (const float*)d_in[8];
    const float* adst2  = (const float*)d_in[9];
    const float* b2     = (const float*)d_in[10];
    const float* p1_sw  = (const float*)d_in[11];
    const float* p1_tw  = (const float*)d_in[13];
    const float* p1_tb  = (const float*)d_in[14];
    const float* p2_sw  = (const float*)d_in[15];
    const float* p2_tw  = (const float*)d_in[17];
    const float* p2_tb  = (const float*)d_in[18];
    const float* c1w    = (const float*)d_in[19];
    const float* c1b    = (const float*)d_in[20];
    const float* c2w    = (const float*)d_in[21];
    const float* c2b    = (const float*)d_in[22];
    float* out = (float*)d_out;

    float*    hlin  = sym(g_hlin);
    float*    hout  = sym(g_hout);
    float*    es    = sym(g_es);
    float*    ed    = sym(g_ed);
    int*      off   = (int*)sym(g_off);
    int*      csrc  = (int*)sym(g_csrc);
    float*    selb  = sym(g_sel);
    float*    pool1 = sym(g_pool1);
    float*    pool2 = sym(g_pool2);

    dim3 t256(256);
    dim3 t128(128);

    // ---- CSR build ----
    csr_build<<<BB, t256>>>(ei);

    // ---- GAT layer 1 (GEMM emits es/ed in epilogue) ----
    sgemm64<<<dim3(CC / 128, NN / 64), t128>>>(x, W1, nullptr, hlin, NN, CC, FIN,
                                               asrc1, adst1, es, ed);
    gat_fused<<<(NN * 32) / 256, t256>>>(off, csrc, es, ed, hlin, b1, hout);

    // ---- GAT layer 2 ----
    sgemm64<<<dim3(CC / 128, NN / 64), t128>>>(hout, W2, nullptr, hlin, NN, CC, CC,
                                               asrc2, adst2, es, ed);
    gat_fused<<<(NN * 32) / 256, t256>>>(off, csrc, es, ed, hlin, b2, hout);

    // ---- Pool 1 (top-256 of 512 per graph) ----
    pool_fused<NPG, K1><<<BB, NPG>>>(hout, p1_sw, selb);
    sgemm64<<<dim3(CC / 128, (BB * K1) / 64), t128>>>(selb, p1_tw, p1_tb, pool1,
                                                      BB * K1, CC, CC,
                                                      nullptr, nullptr, nullptr, nullptr);

    // ---- Pool 2 (top-128 of 256 per graph) ----
    pool_fused<K1, K2><<<BB, K1>>>(pool1, p2_sw, selb);
    sgemm64<<<dim3(CC / 128, (BB * K2) / 64), t128>>>(selb, p2_tw, p2_tb, pool2,
                                                      BB * K2, CC, CC,
                                                      nullptr, nullptr, nullptr, nullptr);

    // ---- readout ----
    readout_fused<<<BB, t256>>>(pool2, c1w, c1b, c2w, c2b, out);
}